// round 1
// baseline (speedup 1.0000x reference)
#include <cuda_runtime.h>

#define B_   8
#define CIN  64
#define COUT 128
#define L_   18
#define LV   16
#define H_   32
#define W_   32
#define HW   1024
#define NH   2
#define DQ   9
#define DV   8

// Scratch (static device globals; no runtime allocation allowed)
__device__ float g_q[B_*COUT*L_*HW];          // 75.5 MB
__device__ float g_k[B_*COUT*L_*HW];          // 75.5 MB
__device__ float g_v[B_*COUT*LV*HW];          // 67 MB
__device__ float g_lp[B_*NH*DQ*COUT*COUT];    // 9.4 MB (split-D logit partials)
__device__ float g_attn[B_*NH*COUT*COUT];     // 1 MB

// ---------------------------------------------------------------------------
// Conv 1x3x3 (depth kernel 1, spatial pad 1) for q and k.
// grid (4 h-tiles, 8 co-groups of 16, B*L), block 256 (8 rows x 32 cols)
// ---------------------------------------------------------------------------
__global__ __launch_bounds__(256) void conv2d_qk_kernel(
    const float* __restrict__ in, const float* __restrict__ wgt,
    const float* __restrict__ bias, float* __restrict__ dst, float scale)
{
    const int tid = threadIdx.x;
    const int hr  = blockIdx.x;
    const int co0 = blockIdx.y << 4;
    const int bl  = blockIdx.z;
    const int b   = bl / L_;
    const int l   = bl % L_;
    const int w   = tid & 31;
    const int h   = (hr << 3) + (tid >> 5);

    __shared__ float ws[CIN*9*16];     // [ci][k][co] for float4 co reads
    for (int i = tid; i < CIN*9*16; i += 256) {
        int co = i & 15;
        int r  = i >> 4;
        int k  = r % 9;
        int ci = r / 9;
        ws[i] = wgt[((co0 + co)*CIN + ci)*9 + k];
    }
    __syncthreads();

    float acc[16];
#pragma unroll
    for (int j = 0; j < 16; j++) acc[j] = 0.f;

    const float* inb = in + (b*CIN*L_ + l)*HW;
    for (int ci = 0; ci < CIN; ci++) {
        const float* p = inb + ci*(L_*HW);
        float iv[9];
#pragma unroll
        for (int kh = 0; kh < 3; kh++) {
            int hh = h + kh - 1;
            bool hv = (unsigned)hh < (unsigned)H_;
            const float* pr = p + hh*W_;
#pragma unroll
            for (int kw = 0; kw < 3; kw++) {
                int ww = w + kw - 1;
                bool v = hv && ((unsigned)ww < (unsigned)W_);
                iv[kh*3 + kw] = v ? pr[ww] : 0.f;
            }
        }
#pragma unroll
        for (int k = 0; k < 9; k++) {
            const float4* wp = (const float4*)&ws[(ci*9 + k) << 4];
            float x = iv[k];
            float4 w0 = wp[0], w1 = wp[1], w2 = wp[2], w3 = wp[3];
            acc[0]  = fmaf(x, w0.x, acc[0]);
            acc[1]  = fmaf(x, w0.y, acc[1]);
            acc[2]  = fmaf(x, w0.z, acc[2]);
            acc[3]  = fmaf(x, w0.w, acc[3]);
            acc[4]  = fmaf(x, w1.x, acc[4]);
            acc[5]  = fmaf(x, w1.y, acc[5]);
            acc[6]  = fmaf(x, w1.z, acc[6]);
            acc[7]  = fmaf(x, w1.w, acc[7]);
            acc[8]  = fmaf(x, w2.x, acc[8]);
            acc[9]  = fmaf(x, w2.y, acc[9]);
            acc[10] = fmaf(x, w2.z, acc[10]);
            acc[11] = fmaf(x, w2.w, acc[11]);
            acc[12] = fmaf(x, w3.x, acc[12]);
            acc[13] = fmaf(x, w3.y, acc[13]);
            acc[14] = fmaf(x, w3.z, acc[14]);
            acc[15] = fmaf(x, w3.w, acc[15]);
        }
    }
#pragma unroll
    for (int j = 0; j < 16; j++) {
        dst[((b*COUT + co0 + j)*L_ + l)*HW + h*W_ + w] =
            (acc[j] + bias[co0 + j]) * scale;
    }
}

// ---------------------------------------------------------------------------
// Conv 3x3x3 (depth valid, spatial pad 1) for v.
// grid (4 h-tiles, 16 co-groups of 8, B*LV), block 256
// ---------------------------------------------------------------------------
__global__ __launch_bounds__(256) void conv3d_v_kernel(
    const float* __restrict__ in, const float* __restrict__ wgt,
    const float* __restrict__ bias, float* __restrict__ dst)
{
    const int tid = threadIdx.x;
    const int hr  = blockIdx.x;
    const int co0 = blockIdx.y << 3;
    const int bl  = blockIdx.z;
    const int b   = bl / LV;
    const int l   = bl % LV;        // output depth, input depths l..l+2
    const int w   = tid & 31;
    const int h   = (hr << 3) + (tid >> 5);

    __shared__ float ws[32*27*8];   // ci-chunked: [ci_local][k][co]
    float acc[8];
#pragma unroll
    for (int j = 0; j < 8; j++) acc[j] = 0.f;

    for (int cc = 0; cc < 2; cc++) {
        const int ci0 = cc << 5;
        __syncthreads();
        for (int i = tid; i < 32*27*8; i += 256) {
            int co = i & 7;
            int r  = i >> 3;
            int k  = r % 27;
            int ci = r / 27;
            ws[i] = wgt[((co0 + co)*CIN + ci0 + ci)*27 + k];
        }
        __syncthreads();
        for (int ci = 0; ci < 32; ci++) {
            const float* p = in + ((b*CIN + ci0 + ci)*L_ + l)*HW;
            float iv[27];
#pragma unroll
            for (int kd = 0; kd < 3; kd++) {
                const float* pd = p + kd*HW;
#pragma unroll
                for (int kh = 0; kh < 3; kh++) {
                    int hh = h + kh - 1;
                    bool hv = (unsigned)hh < (unsigned)H_;
                    const float* pr = pd + hh*W_;
#pragma unroll
                    for (int kw = 0; kw < 3; kw++) {
                        int ww = w + kw - 1;
                        bool v = hv && ((unsigned)ww < (unsigned)W_);
                        iv[(kd*3 + kh)*3 + kw] = v ? pr[ww] : 0.f;
                    }
                }
            }
#pragma unroll
            for (int k = 0; k < 27; k++) {
                const float4* wp = (const float4*)&ws[(ci*27 + k) << 3];
                float x = iv[k];
                float4 w0 = wp[0], w1 = wp[1];
                acc[0] = fmaf(x, w0.x, acc[0]);
                acc[1] = fmaf(x, w0.y, acc[1]);
                acc[2] = fmaf(x, w0.z, acc[2]);
                acc[3] = fmaf(x, w0.w, acc[3]);
                acc[4] = fmaf(x, w1.x, acc[4]);
                acc[5] = fmaf(x, w1.y, acc[5]);
                acc[6] = fmaf(x, w1.z, acc[6]);
                acc[7] = fmaf(x, w1.w, acc[7]);
            }
        }
    }
#pragma unroll
    for (int j = 0; j < 8; j++)
        dst[((b*COUT + co0 + j)*LV + l)*HW + h*W_ + w] = acc[j] + bias[co0 + j];
}

// ---------------------------------------------------------------------------
// Logit partials: per (b, n, d) block computes 128x128 Gram over K = 1024 (h*w).
// Softmax kernel later sums the DQ=9 depth partials. grid 144, block 256.
// ---------------------------------------------------------------------------
__global__ __launch_bounds__(256) void logit_kernel(
    const float* __restrict__ q, const float* __restrict__ k, float* __restrict__ lp)
{
    const int bnd = blockIdx.x;          // (bn, d)
    const int d   = bnd % DQ;
    const int bn  = bnd / DQ;
    const int n   = bn & 1;
    const int b   = bn >> 1;
    const int ldep = n*DQ + d;
    const float* qb = q + (b*COUT*L_ + ldep)*HW;   // row c: + c*L_*HW
    const float* kb = k + (b*COUT*L_ + ldep)*HW;

    __shared__ float As[32*132];         // [kt][c], pad 132 -> aligned float4 + no conflicts
    __shared__ float Bs[32*132];
    const int tid = threadIdx.x;
    const int tx = tid & 15;
    const int ty = tid >> 4;

    float acc[8][8];
#pragma unroll
    for (int i = 0; i < 8; i++)
#pragma unroll
        for (int j = 0; j < 8; j++) acc[i][j] = 0.f;

    for (int p0 = 0; p0 < HW; p0 += 32) {
        __syncthreads();
        for (int i = tid; i < 4096; i += 256) {
            int c  = i >> 5;
            int kt = i & 31;
            As[kt*132 + c] = qb[c*(L_*HW) + p0 + kt];
            Bs[kt*132 + c] = kb[c*(L_*HW) + p0 + kt];
        }
        __syncthreads();
#pragma unroll 4
        for (int kt = 0; kt < 32; kt++) {
            float4 a0 = *(const float4*)&As[kt*132 + ty*8];
            float4 a1 = *(const float4*)&As[kt*132 + ty*8 + 4];
            float4 b0 = *(const float4*)&Bs[kt*132 + tx*8];
            float4 b1 = *(const float4*)&Bs[kt*132 + tx*8 + 4];
            float av[8] = {a0.x,a0.y,a0.z,a0.w,a1.x,a1.y,a1.z,a1.w};
            float bv[8] = {b0.x,b0.y,b0.z,b0.w,b1.x,b1.y,b1.z,b1.w};
#pragma unroll
            for (int ii = 0; ii < 8; ii++)
#pragma unroll
                for (int jj = 0; jj < 8; jj++)
                    acc[ii][jj] = fmaf(av[ii], bv[jj], acc[ii][jj]);
        }
    }
    float* o = lp + bnd*COUT*COUT;
#pragma unroll
    for (int ii = 0; ii < 8; ii++)
#pragma unroll
        for (int jj = 0; jj < 8; jj++)
            o[(ty*8 + ii)*COUT + tx*8 + jj] = acc[ii][jj];
}

// ---------------------------------------------------------------------------
// Sum depth partials + row softmax over m (128). One block per (bn, c) row.
// ---------------------------------------------------------------------------
__global__ __launch_bounds__(128) void softmax_kernel(
    const float* __restrict__ lp, float* __restrict__ attn)
{
    const int row = blockIdx.x;          // bn*128 + c
    const int bn  = row >> 7;
    const int c   = row & 127;
    const int m   = threadIdx.x;

    float s = 0.f;
#pragma unroll
    for (int dd = 0; dd < DQ; dd++)
        s += lp[((bn*DQ + dd)*COUT + c)*COUT + m];

    __shared__ float red[128];
    red[m] = s;
    __syncthreads();
    for (int off = 64; off > 0; off >>= 1) {
        if (m < off) red[m] = fmaxf(red[m], red[m + off]);
        __syncthreads();
    }
    float mx = red[0];
    __syncthreads();
    float e = expf(s - mx);
    red[m] = e;
    __syncthreads();
    for (int off = 64; off > 0; off >>= 1) {
        if (m < off) red[m] = red[m] + red[m + off];
        __syncthreads();
    }
    attn[row*COUT + m] = e / red[0];
}

// ---------------------------------------------------------------------------
// out[b,c,n*8+d,hw] = sum_m attn[bn,c,m] * v[b,m,n*8+d,hw]
// grid (128 pixel tiles of 64, 16 bn), block 256 = 4 c-groups x 64 pixels,
// each thread 32 output channels.
// ---------------------------------------------------------------------------
__global__ __launch_bounds__(256) void out_kernel(
    const float* __restrict__ attn, const float* __restrict__ v, float* __restrict__ out)
{
    const int tile = blockIdx.x;         // 0..127 over d*hw
    const int bn   = blockIdx.y;
    const int b    = bn >> 1;
    const int n    = bn & 1;
    const int d    = (tile << 6) >> 10;  // 64 | 1024, tile lies in one depth
    const int hw0  = (tile << 6) & 1023;
    const int tid  = threadIdx.x;
    const int px   = tid & 63;
    const int cg   = tid >> 6;
    const int c0   = cg << 5;
    const int hw   = hw0 + px;

    __shared__ float As[64*132];         // attn chunk transposed: [m_local][c]
    const float* ab = attn + bn*COUT*COUT;
    const float* vb = v + (b*COUT*LV + n*DV + d)*HW + hw;   // + m*LV*HW

    float acc[32];
#pragma unroll
    for (int j = 0; j < 32; j++) acc[j] = 0.f;

    for (int mc = 0; mc < 2; mc++) {
        __syncthreads();
        for (int i = tid; i < 64*128; i += 256) {
            int ml = i & 63;
            int c  = i >> 6;
            As[ml*132 + c] = ab[c*COUT + (mc << 6) + ml];
        }
        __syncthreads();
#pragma unroll 4
        for (int ml = 0; ml < 64; ml++) {
            float vv = vb[((mc << 6) + ml)*(LV*HW)];
            const float4* ap = (const float4*)&As[ml*132 + c0];
#pragma unroll
            for (int jj = 0; jj < 8; jj++) {
                float4 a = ap[jj];
                acc[jj*4 + 0] = fmaf(a.x, vv, acc[jj*4 + 0]);
                acc[jj*4 + 1] = fmaf(a.y, vv, acc[jj*4 + 1]);
                acc[jj*4 + 2] = fmaf(a.z, vv, acc[jj*4 + 2]);
                acc[jj*4 + 3] = fmaf(a.w, vv, acc[jj*4 + 3]);
            }
        }
    }
    float* ob = out + ((b*COUT + c0)*(NH*DV) + n*DV + d)*HW + hw;
#pragma unroll
    for (int j = 0; j < 32; j++)
        ob[j*(NH*DV*HW)] = acc[j];
}

// ---------------------------------------------------------------------------
extern "C" void kernel_launch(void* const* d_in, const int* in_sizes, int n_in,
                              void* d_out, int out_size)
{
    const float* input  = (const float*)d_in[0];
    const float* memory = (const float*)d_in[1];
    const float* wq = (const float*)d_in[2];
    const float* bq = (const float*)d_in[3];
    const float* wk = (const float*)d_in[4];
    const float* bk = (const float*)d_in[5];
    const float* wv = (const float*)d_in[6];
    const float* bv = (const float*)d_in[7];
    float* out = (float*)d_out;

    float *pq, *pk, *pv, *plp, *pattn;
    cudaGetSymbolAddress((void**)&pq,    g_q);
    cudaGetSymbolAddress((void**)&pk,    g_k);
    cudaGetSymbolAddress((void**)&pv,    g_v);
    cudaGetSymbolAddress((void**)&plp,   g_lp);
    cudaGetSymbolAddress((void**)&pattn, g_attn);

    conv2d_qk_kernel<<<dim3(4, 8, B_*L_), 256>>>(input,  wq, bq, pq, 0.5f);
    conv2d_qk_kernel<<<dim3(4, 8, B_*L_), 256>>>(memory, wk, bk, pk, 1.0f);
    conv3d_v_kernel <<<dim3(4, 16, B_*LV), 256>>>(memory, wv, bv, pv);
    logit_kernel    <<<B_*NH*DQ, 256>>>(pq, pk, plp);
    softmax_kernel  <<<B_*NH*COUT, 128>>>(plp, pattn);
    out_kernel      <<<dim3(128, B_*NH), 256>>>(pattn, pv, out);
}

// round 3
// speedup vs baseline: 1.4938x; 1.4938x over previous
#include <cuda_runtime.h>

#define B_   8
#define CIN  64
#define COUT 128
#define L_   18
#define LV   16
#define H_   32
#define W_   32
#define HW   1024
#define NH   2
#define DQ   9
#define DV   8
#define KSPLIT 4

// Scratch (static device globals; no runtime allocation allowed)
__device__ float g_q[B_*COUT*L_*HW];                 // 75.5 MB
__device__ float g_k[B_*COUT*L_*HW];                 // 75.5 MB
__device__ float g_v[B_*COUT*LV*HW];                 // 67 MB
__device__ float g_lp[KSPLIT*B_*NH*DQ*COUT*COUT];    // 37.7 MB (split K+D logit partials)
__device__ float g_attn[B_*NH*COUT*COUT];            // 1 MB

typedef unsigned long long ull;

__device__ __forceinline__ ull pack2(float x, float y) {
    ull r; asm("mov.b64 %0, {%1, %2};" : "=l"(r) : "f"(x), "f"(y)); return r;
}
__device__ __forceinline__ float2 unpack2(ull v) {
    float2 r; asm("mov.b64 {%0, %1}, %2;" : "=f"(r.x), "=f"(r.y) : "l"(v)); return r;
}
__device__ __forceinline__ void ffma2(ull& d, ull a, ull b) {
    asm("fma.rn.f32x2 %0, %1, %2, %0;" : "+l"(d) : "l"(a), "l"(b));
}

// ---------------------------------------------------------------------------
// Conv 1x3x3 (depth kernel 1, spatial pad 1) for q and k.
// grid (2 h-tiles, 8 co-groups of 16, B*L), block 256 = 32 w x 8 h-pairs.
// Each thread: 2 adjacent-h pixels x 16 output channels (8 f32x2 pairs).
// ---------------------------------------------------------------------------
__global__ __launch_bounds__(256) void conv2d_qk_kernel(
    const float* __restrict__ in, const float* __restrict__ wgt,
    const float* __restrict__ bias, float* __restrict__ dst, float scale)
{
    const int tid = threadIdx.x;
    const int co0 = blockIdx.y << 4;
    const int bl  = blockIdx.z;
    const int b   = bl / L_;
    const int l   = bl % L_;
    const int w   = tid & 31;
    const int h0  = (blockIdx.x << 4) + ((tid >> 5) << 1);   // even row; pixels h0, h0+1

    __shared__ float ws[CIN*9*16];     // [ci][k][co], co pairs are u64-aligned
    for (int i = tid; i < CIN*9*16; i += 256) {
        int co = i & 15;
        int r  = i >> 4;
        int k  = r % 9;
        int ci = r / 9;
        ws[i] = wgt[((co0 + co)*CIN + ci)*9 + k];
    }
    __syncthreads();

    ull acc0[8], acc1[8];
#pragma unroll
    for (int j = 0; j < 8; j++) { acc0[j] = 0ull; acc1[j] = 0ull; }

    const float* inb = in + (b*CIN*L_ + l)*HW;
    for (int ci = 0; ci < CIN; ci++) {
        const float* p = inb + ci*(L_*HW);
        ull xp[4][3];                  // rows h0-1..h0+2, kw -1..+1, each (x,x)
#pragma unroll
        for (int r = 0; r < 4; r++) {
            int hh = h0 - 1 + r;
            bool hv = (unsigned)hh < (unsigned)H_;
            const float* pr = p + hh*W_;
#pragma unroll
            for (int c = 0; c < 3; c++) {
                int ww = w + c - 1;
                float x = (hv && (unsigned)ww < (unsigned)W_) ? pr[ww] : 0.f;
                xp[r][c] = pack2(x, x);
            }
        }
#pragma unroll
        for (int kh = 0; kh < 3; kh++) {
#pragma unroll
            for (int kw = 0; kw < 3; kw++) {
                const ull* wp = (const ull*)&ws[(ci*9 + kh*3 + kw) << 4];
                ull wv[8];
#pragma unroll
                for (int j = 0; j < 8; j++) wv[j] = wp[j];
                ull x0 = xp[kh][kw];
                ull x1 = xp[kh + 1][kw];
#pragma unroll
                for (int j = 0; j < 8; j++) {
                    ffma2(acc0[j], x0, wv[j]);
                    ffma2(acc1[j], x1, wv[j]);
                }
            }
        }
    }
#pragma unroll
    for (int j = 0; j < 8; j++) {
        float2 a0 = unpack2(acc0[j]);
        float2 a1 = unpack2(acc1[j]);
        int c0 = co0 + 2*j, c1 = c0 + 1;
        float b0 = bias[c0], b1 = bias[c1];
        float* d0 = dst + ((b*COUT + c0)*L_ + l)*HW + h0*W_ + w;
        float* d1 = dst + ((b*COUT + c1)*L_ + l)*HW + h0*W_ + w;
        d0[0]  = (a0.x + b0) * scale;
        d0[W_] = (a1.x + b0) * scale;
        d1[0]  = (a0.y + b1) * scale;
        d1[W_] = (a1.y + b1) * scale;
    }
}

// ---------------------------------------------------------------------------
// Conv 3x3x3 (depth valid, spatial pad 1) for v.
// grid (2 h-tiles, 8 co-groups of 16, B*LV), block 256.
// Each thread: 2 adjacent-h pixels x 16 output channels.
// ---------------------------------------------------------------------------
__global__ __launch_bounds__(256) void conv3d_v_kernel(
    const float* __restrict__ in, const float* __restrict__ wgt,
    const float* __restrict__ bias, float* __restrict__ dst)
{
    const int tid = threadIdx.x;
    const int co0 = blockIdx.y << 4;
    const int bl  = blockIdx.z;
    const int b   = bl / LV;
    const int l   = bl % LV;        // output depth, input depths l..l+2
    const int w   = tid & 31;
    const int h0  = (blockIdx.x << 4) + ((tid >> 5) << 1);

    __shared__ float ws[32*27*16];  // ci-chunked: [ci_local][k][co] (55 KB)

    ull acc0[8], acc1[8];
#pragma unroll
    for (int j = 0; j < 8; j++) { acc0[j] = 0ull; acc1[j] = 0ull; }

    for (int cc = 0; cc < 2; cc++) {
        const int ci0 = cc << 5;
        __syncthreads();
        for (int i = tid; i < 32*27*16; i += 256) {
            int co = i & 15;
            int r  = i >> 4;
            int k  = r % 27;
            int ci = r / 27;
            ws[i] = wgt[((co0 + co)*CIN + ci0 + ci)*27 + k];
        }
        __syncthreads();
        for (int ci = 0; ci < 32; ci++) {
            const float* p = in + ((b*CIN + ci0 + ci)*L_ + l)*HW;
#pragma unroll
            for (int kd = 0; kd < 3; kd++) {
                const float* pd = p + kd*HW;
                ull xp[4][3];
#pragma unroll
                for (int r = 0; r < 4; r++) {
                    int hh = h0 - 1 + r;
                    bool hv = (unsigned)hh < (unsigned)H_;
                    const float* pr = pd + hh*W_;
#pragma unroll
                    for (int c = 0; c < 3; c++) {
                        int ww = w + c - 1;
                        float x = (hv && (unsigned)ww < (unsigned)W_) ? pr[ww] : 0.f;
                        xp[r][c] = pack2(x, x);
                    }
                }
#pragma unroll
                for (int kh = 0; kh < 3; kh++) {
#pragma unroll
                    for (int kw = 0; kw < 3; kw++) {
                        const ull* wp = (const ull*)&ws[(ci*27 + kd*9 + kh*3 + kw) << 4];
                        ull wv[8];
#pragma unroll
                        for (int j = 0; j < 8; j++) wv[j] = wp[j];
                        ull x0 = xp[kh][kw];
                        ull x1 = xp[kh + 1][kw];
#pragma unroll
                        for (int j = 0; j < 8; j++) {
                            ffma2(acc0[j], x0, wv[j]);
                            ffma2(acc1[j], x1, wv[j]);
                        }
                    }
                }
            }
        }
    }
#pragma unroll
    for (int j = 0; j < 8; j++) {
        float2 a0 = unpack2(acc0[j]);
        float2 a1 = unpack2(acc1[j]);
        int c0 = co0 + 2*j, c1 = c0 + 1;
        float b0 = bias[c0], b1 = bias[c1];
        float* d0 = dst + ((b*COUT + c0)*LV + l)*HW + h0*W_ + w;
        float* d1 = dst + ((b*COUT + c1)*LV + l)*HW + h0*W_ + w;
        d0[0]  = a0.x + b0;
        d0[W_] = a1.x + b0;
        d1[0]  = a0.y + b1;
        d1[W_] = a1.y + b1;
    }
}

// ---------------------------------------------------------------------------
// Logit partials: per (chunk, b, n, d) block computes 128x128 Gram over
// K = 256 pixels. grid 576, block 256, 8x8 register tile with f32x2 on jj.
// ---------------------------------------------------------------------------
__global__ __launch_bounds__(256) void logit_kernel(
    const float* __restrict__ q, const float* __restrict__ k, float* __restrict__ lp)
{
    const int bnd   = blockIdx.x % (B_*NH*DQ);
    const int chunk = blockIdx.x / (B_*NH*DQ);
    const int d   = bnd % DQ;
    const int bn  = bnd / DQ;
    const int n   = bn & 1;
    const int b   = bn >> 1;
    const int ldep = n*DQ + d;
    const float* qb = q + (b*COUT*L_ + ldep)*HW;   // row c: + c*L_*HW
    const float* kb = k + (b*COUT*L_ + ldep)*HW;

    __shared__ float As[32*132];         // [kt][c], pad 132 (528B: 16B-aligned rows)
    __shared__ float Bs[32*132];
    const int tid = threadIdx.x;
    const int tx = tid & 15;
    const int ty = tid >> 4;

    ull acc2[8][4];
#pragma unroll
    for (int i = 0; i < 8; i++)
#pragma unroll
        for (int j = 0; j < 4; j++) acc2[i][j] = 0ull;

    const int p_base = chunk * (HW / KSPLIT);
    for (int p0 = p_base; p0 < p_base + HW/KSPLIT; p0 += 32) {
        __syncthreads();
        for (int i = tid; i < 4096; i += 256) {
            int c  = i >> 5;
            int kt = i & 31;
            As[kt*132 + c] = qb[c*(L_*HW) + p0 + kt];
            Bs[kt*132 + c] = kb[c*(L_*HW) + p0 + kt];
        }
        __syncthreads();
#pragma unroll 4
        for (int kt = 0; kt < 32; kt++) {
            float4 a0 = *(const float4*)&As[kt*132 + ty*8];
            float4 a1 = *(const float4*)&As[kt*132 + ty*8 + 4];
            const ull* bp = (const ull*)&Bs[kt*132 + tx*8];
            ull bv[4];
#pragma unroll
            for (int j = 0; j < 4; j++) bv[j] = bp[j];
            float av[8] = {a0.x,a0.y,a0.z,a0.w,a1.x,a1.y,a1.z,a1.w};
#pragma unroll
            for (int ii = 0; ii < 8; ii++) {
                ull ap = pack2(av[ii], av[ii]);
#pragma unroll
                for (int jj = 0; jj < 4; jj++)
                    ffma2(acc2[ii][jj], ap, bv[jj]);
            }
        }
    }
    float* o = lp + (size_t)blockIdx.x*COUT*COUT;
#pragma unroll
    for (int ii = 0; ii < 8; ii++)
#pragma unroll
        for (int jj = 0; jj < 4; jj++) {
            float2 v = unpack2(acc2[ii][jj]);
            o[(ty*8 + ii)*COUT + tx*8 + 2*jj]     = v.x;
            o[(ty*8 + ii)*COUT + tx*8 + 2*jj + 1] = v.y;
        }
}

// ---------------------------------------------------------------------------
// Sum KSPLIT*DQ partials + row softmax over m (128). One block per (bn, c).
// ---------------------------------------------------------------------------
__global__ __launch_bounds__(128) void softmax_kernel(
    const float* __restrict__ lp, float* __restrict__ attn)
{
    const int row = blockIdx.x;          // bn*128 + c
    const int bn  = row >> 7;
    const int c   = row & 127;
    const int m   = threadIdx.x;

    float s = 0.f;
#pragma unroll
    for (int ch = 0; ch < KSPLIT; ch++)
#pragma unroll
        for (int dd = 0; dd < DQ; dd++)
            s += lp[(((size_t)(ch*(B_*NH*DQ) + bn*DQ + dd))*COUT + c)*COUT + m];

    __shared__ float red[128];
    red[m] = s;
    __syncthreads();
    for (int off = 64; off > 0; off >>= 1) {
        if (m < off) red[m] = fmaxf(red[m], red[m + off]);
        __syncthreads();
    }
    float mx = red[0];
    __syncthreads();
    float e = expf(s - mx);
    red[m] = e;
    __syncthreads();
    for (int off = 64; off > 0; off >>= 1) {
        if (m < off) red[m] = red[m] + red[m + off];
        __syncthreads();
    }
    attn[row*COUT + m] = e / red[0];
}

// ---------------------------------------------------------------------------
// out[b,c,n*8+d,hw] = sum_m attn[bn,c,m] * v[b,m,n*8+d,hw]
// grid (128 pixel tiles of 64, 16 bn), block 256; thread: 32 couts (16 f32x2).
// ---------------------------------------------------------------------------
__global__ __launch_bounds__(256) void out_kernel(
    const float* __restrict__ attn, const float* __restrict__ v, float* __restrict__ out)
{
    const int tile = blockIdx.x;         // 0..127 over d*hw
    const int bn   = blockIdx.y;
    const int b    = bn >> 1;
    const int n    = bn & 1;
    const int d    = (tile << 6) >> 10;
    const int hw0  = (tile << 6) & 1023;
    const int tid  = threadIdx.x;
    const int px   = tid & 63;
    const int cg   = tid >> 6;
    const int c0   = cg << 5;
    const int hw   = hw0 + px;

    __shared__ float As[64*132];         // attn chunk transposed: [m_local][c]
    const float* ab = attn + bn*COUT*COUT;
    const float* vb = v + (b*COUT*LV + n*DV + d)*HW + hw;

    ull acc2[16];
#pragma unroll
    for (int j = 0; j < 16; j++) acc2[j] = 0ull;

    for (int mc = 0; mc < 2; mc++) {
        __syncthreads();
        for (int i = tid; i < 64*128; i += 256) {
            int ml = i & 63;
            int c  = i >> 6;
            As[ml*132 + c] = ab[c*COUT + (mc << 6) + ml];
        }
        __syncthreads();
#pragma unroll 4
        for (int ml = 0; ml < 64; ml++) {
            float vv = vb[((mc << 6) + ml)*(LV*HW)];
            ull vp = pack2(vv, vv);
            const ull* ap = (const ull*)&As[ml*132 + c0];
#pragma unroll
            for (int jj = 0; jj < 16; jj++)
                ffma2(acc2[jj], ap[jj], vp);
        }
    }
    float* ob = out + ((b*COUT + c0)*(NH*DV) + n*DV + d)*HW + hw;
#pragma unroll
    for (int jj = 0; jj < 16; jj++) {
        float2 a = unpack2(acc2[jj]);
        ob[(2*jj)    *(NH*DV*HW)] = a.x;
        ob[(2*jj + 1)*(NH*DV*HW)] = a.y;
    }
}

// ---------------------------------------------------------------------------
extern "C" void kernel_launch(void* const* d_in, const int* in_sizes, int n_in,
                              void* d_out, int out_size)
{
    const float* input  = (const float*)d_in[0];
    const float* memory = (const float*)d_in[1];
    const float* wq = (const float*)d_in[2];
    const float* bq = (const float*)d_in[3];
    const float* wk = (const float*)d_in[4];
    const float* bk = (const float*)d_in[5];
    const float* wv = (const float*)d_in[6];
    const float* bv = (const float*)d_in[7];
    float* out = (float*)d_out;

    float *pq, *pk, *pv, *plp, *pattn;
    cudaGetSymbolAddress((void**)&pq,    g_q);
    cudaGetSymbolAddress((void**)&pk,    g_k);
    cudaGetSymbolAddress((void**)&pv,    g_v);
    cudaGetSymbolAddress((void**)&plp,   g_lp);
    cudaGetSymbolAddress((void**)&pattn, g_attn);

    conv2d_qk_kernel<<<dim3(2, 8, B_*L_), 256>>>(input,  wq, bq, pq, 0.5f);
    conv2d_qk_kernel<<<dim3(2, 8, B_*L_), 256>>>(memory, wk, bk, pk, 1.0f);
    conv3d_v_kernel <<<dim3(2, 8, B_*LV), 256>>>(memory, wv, bv, pv);
    logit_kernel    <<<KSPLIT*B_*NH*DQ, 256>>>(pq, pk, plp);
    softmax_kernel  <<<B_*NH*COUT, 128>>>(plp, pattn);
    out_kernel      <<<dim3(128, B_*NH), 256>>>(pattn, pv, out);
}